// round 15
// baseline (speedup 1.0000x reference)
#include <cuda_runtime.h>
#include <cuda_bf16.h>
#include <math.h>

#define Nn 2048
#define Uu 64
#define ALPHA 1.0f

// ---------------- scratch (no allocations allowed) ----------------
__device__ __nv_bfloat16 g_Lh[(size_t)Nn * Nn];        // 8 MB: E = exp(logits), bf16
__device__ float g_colpart[32 * Nn];                   // partial column sums (fp32)
__device__ float g_head[Nn];
__device__ float g_c[Nn];                              // c[j] = (f[j]·w2)/S_j
__device__ float g_rr[Nn];                             // return ratio per row

// ---------------- K1: head scores ----------------
__global__ void k_init(const float* __restrict__ feature,
                       const float* __restrict__ head_w,
                       const float* __restrict__ head_b) {
    int i = blockIdx.x * blockDim.x + threadIdx.x;
    if (i >= Nn) return;
    const float4* fr = (const float4*)(feature + (size_t)i * Uu);
    const float4* hw = (const float4*)head_w;
    float4 a4 = make_float4(0.f, 0.f, 0.f, 0.f);
#pragma unroll
    for (int k = 0; k < 16; k++) {
        float4 a = fr[k], w = hw[k];
        a4.x += a.x * w.x; a4.y += a.y * w.y; a4.z += a.z * w.z; a4.w += a.w * w.w;
    }
    g_head[i] = fmaxf((a4.x + a4.y) + (a4.z + a4.w) + head_b[0], 0.f);
}

// ---------------- K2: 1 GiB stream, warp-cooperative, fused exp + colsum ----
// 8 lanes per pair, 4 pairs per warp -> each warp-iteration reads 1KB
// contiguous. Colsum accumulated in fp32; E stored bf16 (dot-side only).
__global__ void k_rel_exp(const float* __restrict__ relation,
                          const float* __restrict__ rel_w,
                          const float* __restrict__ rel_b,
                          const float* __restrict__ rel_mask) {
    __shared__ float s_head[64];
    const int t  = threadIdx.x;
    const int w  = t >> 5;          // warp in block (0-7)
    const int l  = t & 31;          // lane
    const int g  = l >> 3;          // pair group within warp (0-3)
    const int k  = l & 7;           // element slot within pair
    const int j0 = blockIdx.x * 32 + w * 4;   // warp's 4 columns
    const int i0 = blockIdx.y * 64;           // block's 64 rows

    if (t < 64) s_head[t] = g_head[i0 + t];
    __syncthreads();

    const float rb = rel_b[0];
    const float4 wa = __ldg(&((const float4*)rel_w)[k]);
    const float4 wb = __ldg(&((const float4*)rel_w)[k + 8]);

    const float4* base = (const float4*)relation + ((size_t)i0 * Nn + j0) * 16;
    const int o1 = g * 16 + k;      // lane's fixed float4 offsets in 1KB span
    const int o2 = o1 + 8;

    float colsum = 0.f;
#pragma unroll 8
    for (int r = 0; r < 64; r++) {
        const float4* rowp = base + (size_t)r * (Nn * 16);
        float4 a = rowp[o1];
        float4 b = rowp[o2];
        float d = a.x * wa.x + a.y * wa.y + a.z * wa.z + a.w * wa.w
                + b.x * wb.x + b.y * wb.y + b.z * wb.z + b.w * wb.w;
        d += __shfl_xor_sync(0xffffffffu, d, 1);
        d += __shfl_xor_sync(0xffffffffu, d, 2);
        d += __shfl_xor_sync(0xffffffffu, d, 4);
        float s = __shfl_sync(0xffffffffu, d, (l * 8) & 31);
        if (l < 4) {
            size_t p = (size_t)(i0 + r) * Nn + j0 + l;
            float logit = fmaxf(s + rb, 0.f) + rel_mask[p] + s_head[r];
            float e = __expf(logit);
            g_Lh[p] = __float2bfloat16_rn(e);
            colsum += e;
        }
    }
    if (l < 4)
        g_colpart[(size_t)blockIdx.y * Nn + j0 + l] = colsum;
}

// ---------------- K3: c[j] = (feature[j,:]·pred_w[64:128]) / S_j ------------
__global__ void k_colc(const float* __restrict__ feature,
                       const float* __restrict__ pred_w) {
    int j = blockIdx.x * blockDim.x + threadIdx.x;
    if (j >= Nn) return;
    float s = 0.f;
#pragma unroll
    for (int c = 0; c < 32; c++) s += g_colpart[(size_t)c * Nn + j];
    const float4* fr = (const float4*)(feature + (size_t)j * Uu);
    const float4* w2 = (const float4*)(pred_w + Uu);
    float4 a4 = make_float4(0.f, 0.f, 0.f, 0.f);
#pragma unroll
    for (int k = 0; k < 16; k++) {
        float4 a = fr[k], w = w2[k];
        a4.x += a.x * w.x; a4.y += a.y * w.y; a4.z += a.z * w.z; a4.w += a.w * w.w;
    }
    g_c[j] = ((a4.x + a4.y) + (a4.z + a4.w)) / s;
}

// ---------------- K4: prediction matvec + return ratio (block per row) -----
// Thread t loads exactly uint4 #t of row i (256 x 8 bf16 = the full row).
// No fences, no atomics: pure stream + two-stage reduction.
__global__ void k_dotpred(const float* __restrict__ feature,
                          const float* __restrict__ pred_w,
                          const float* __restrict__ pred_b,
                          const float* __restrict__ base_price) {
    const int i = blockIdx.x;
    const int t = threadIdx.x;
    const int l = t & 31;
    const int w = t >> 5;
    __shared__ float s_part[8];

    // E[i, 8t..8t+8) · c[8t..8t+8)
    uint4 raw = ((const uint4*)(g_Lh + (size_t)i * Nn))[t];
    float4 c0 = ((const float4*)g_c)[2 * t];
    float4 c1 = ((const float4*)g_c)[2 * t + 1];
    const __nv_bfloat162* eb = (const __nv_bfloat162*)&raw;
    float2 e0 = __bfloat1622float2(eb[0]);
    float2 e1 = __bfloat1622float2(eb[1]);
    float2 e2 = __bfloat1622float2(eb[2]);
    float2 e3 = __bfloat1622float2(eb[3]);
    float acc = e0.x * c0.x + e0.y * c0.y + e1.x * c0.z + e1.y * c0.w
              + e2.x * c1.x + e2.y * c1.y + e3.x * c1.z + e3.y * c1.w;
#pragma unroll
    for (int o = 16; o > 0; o >>= 1)
        acc += __shfl_xor_sync(0xffffffffu, acc, o);
    if (l == 0) s_part[w] = acc;
    __syncthreads();

    if (w == 0) {
        // E-part total (lanes 0-7 hold the 8 warp partials)
        float esum = (l < 8) ? s_part[l] : 0.f;
        esum += __shfl_xor_sync(0xffffffffu, esum, 4);
        esum += __shfl_xor_sync(0xffffffffu, esum, 2);
        esum += __shfl_xor_sync(0xffffffffu, esum, 1);
        // feature half: lane l owns u-pair [2l, 2l+1]
        float2 f  = ((const float2*)(feature + (size_t)i * Uu))[l];
        float2 w1 = ((const float2*)pred_w)[l];
        float facc = f.x * w1.x + f.y * w1.y;
#pragma unroll
        for (int o = 16; o > 0; o >>= 1)
            facc += __shfl_xor_sync(0xffffffffu, facc, o);
        if (l == 0) {
            float dot = esum + facc + pred_b[0];
            float pred = dot >= 0.f ? dot : 0.2f * dot;
            float bp = base_price[i];
            g_rr[i] = (pred - bp) / bp;
        }
    }
}

// ---------------- K5: final losses (single block, fixed order) ----------------
__global__ void k_final(const float* __restrict__ ground_truth,
                        const float* __restrict__ mask,
                        float* __restrict__ out, int out_size) {
    __shared__ float s_reg[256], s_p[256], s_n[256];
    const int t = threadIdx.x;
    float reg = 0.f, p = 0.f, ng = 0.f;
    for (int r = t; r < Nn; r += 256) {
        float rr = g_rr[r];
        float d = rr - ground_truth[r];
        reg += d * d;
        float x = rr * mask[r];
        p  += fmaxf(x, 0.f);
        ng += fminf(x, 0.f);
    }
    s_reg[t] = reg; s_p[t] = p; s_n[t] = ng;
    __syncthreads();
    for (int st = 128; st > 0; st >>= 1) {
        if (t < st) {
            s_reg[t] += s_reg[t + st];
            s_p[t]   += s_p[t + st];
            s_n[t]   += s_n[t + st];
        }
        __syncthreads();
    }
    if (t == 0) {
        float regl = s_reg[0];
        float P = s_p[0], Ng = s_n[0];
        float rank = (P * P + Ng * Ng) / ((float)Nn * (float)Nn);
        float loss = regl + ALPHA * rank;
        if (out_size >= 1) out[0] = loss;
        if (out_size >= 2) out[1] = regl;
        if (out_size >= 3) out[2] = rank;
    }
}

// ---------------- launch ----------------
extern "C" void kernel_launch(void* const* d_in, const int* in_sizes, int n_in,
                              void* d_out, int out_size) {
    const float* feature      = (const float*)d_in[0];
    const float* relation     = (const float*)d_in[1];
    const float* rel_mask     = (const float*)d_in[2];
    const float* base_price   = (const float*)d_in[3];
    const float* ground_truth = (const float*)d_in[4];
    const float* mask         = (const float*)d_in[5];
    const float* rel_w        = (const float*)d_in[6];
    const float* rel_b        = (const float*)d_in[7];
    const float* head_w       = (const float*)d_in[8];
    const float* head_b       = (const float*)d_in[9];
    // tail_w/tail_b (10/11) dead: tail[j] constant per softmax column (axis 0)
    const float* pred_w       = (const float*)d_in[12];
    const float* pred_b       = (const float*)d_in[13];
    float* out = (float*)d_out;

    k_init<<<(Nn + 255) / 256, 256>>>(feature, head_w, head_b);
    {
        dim3 g(Nn / 32, Nn / 64);          // 64 x 32 = 2048 blocks
        k_rel_exp<<<g, 256>>>(relation, rel_w, rel_b, rel_mask);
    }
    k_colc<<<(Nn + 255) / 256, 256>>>(feature, pred_w);
    k_dotpred<<<Nn, 256>>>(feature, pred_w, pred_b, base_price);
    k_final<<<1, 256>>>(ground_truth, mask, out, out_size);
}